// round 3
// baseline (speedup 1.0000x reference)
#include <cuda_runtime.h>
#include <cstdint>
#include <math.h>

#define DET 512
#define NTH 180
#define B   4
#define OUT 362
#define RAD 181          // OUT/2 (=181 per reference: radius = 362//2)
#define PI_F 3.14159265358979323846f

#define ROWLEN 516       // 512 data + 4 pad (zeros); 516*4 bytes, 16B-divisible
#define OOB    513       // pad slot: row[513]=row[514]=0

// filtered projections, layout [b][a][det] (det contiguous)
__device__ float g_filt[B * NTH * DET];

// ---------------------------------------------------------------------------
// Kernel 1: ramp filter as direct symmetric convolution (exact circular conv
// equivalent of the reference's FFT ramp filtering with 512-zero pad).
// ---------------------------------------------------------------------------
__global__ void __launch_bounds__(DET) filter_kernel(const float* __restrict__ x)
{
    __shared__ float xs[DET];
    __shared__ float gt[DET];

    const int a = blockIdx.x;
    const int b = blockIdx.y;
    const int k = threadIdx.x;

    // x layout: (B,1,DET,NTH) -> x[b, m, a] = x[(b*DET + m)*NTH + a]
    xs[k] = x[(b * DET + k) * NTH + a];

    float fd = (float)k;
    gt[k] = (k & 1) ? (-2.0f / (PI_F * PI_F * fd * fd)) : 0.0f;
    __syncthreads();

    float s = 0.5f * xs[k];
    const int par = (k & 1) ^ 1;   // m-parity opposite to k
    #pragma unroll 8
    for (int i = 0; i < DET / 2; i++) {
        int m = 2 * i + par;
        int d = k - m; d = d < 0 ? -d : d;
        s = fmaf(gt[d], xs[m], s);
    }
    g_filt[(b * NTH + a) * DET + k] = s;
}

// ---------------------------------------------------------------------------
// Kernel 2: backprojection.
// 32x32 pixel tile, TWO batches per block (shared address math), 256 threads,
// 4 pixel-rows per thread. cp.async double-buffered row staging.
// pos = (j-RAD)*cos(th) - (i-RAD)*sin(th) + DET/2
// ---------------------------------------------------------------------------
__global__ void __launch_bounds__(256) backproj_kernel(float* __restrict__ out)
{
    // double buffer: [stage][batch][ROWLEN]
    __shared__ float rows[2][2][ROWLEN];
    __shared__ float cs[NTH];
    __shared__ float sn[NTH];

    const int b0 = blockIdx.z * 2;       // batches b0, b0+1
    const int j0 = blockIdx.x * 32;
    const int i0 = blockIdx.y * 32;
    const int tid = threadIdx.x;
    const int tx = tid & 31;             // column j within tile
    const int ty = tid >> 5;             // 0..7, pixel-row group

    if (tid < NTH) {
        float ang = (float)tid * (PI_F / 180.0f);
        cs[tid] = cosf(ang);
        sn[tid] = sinf(ang);
    }
    // zero the pad slots (never overwritten by cp.async)
    if (tid < 8) {
        int st = tid & 1, bb = (tid >> 1) & 1, p = tid >> 2;
        rows[st][bb][512 + 2 * p]     = 0.0f;
        rows[st][bb][512 + 2 * p + 1] = 0.0f;
    }

    // staging assignment: thread copies 16B; r_st = which batch row, c16 = chunk
    const int r_st  = tid >> 7;          // 0 or 1
    const int c16   = tid & 127;         // 16B chunk within the 2KB row
    const float* gsrc_base = g_filt + ((b0 + r_st) * NTH) * DET + c16 * 4;
    unsigned int sdst[2];
    {
        unsigned int s0, s1;
        asm("{ .reg .u64 t; cvta.to.shared.u64 t, %1; cvt.u32.u64 %0, t; }"
            : "=r"(s0) : "l"((const void*)&rows[0][r_st][c16 * 4]));
        asm("{ .reg .u64 t; cvta.to.shared.u64 t, %1; cvt.u32.u64 %0, t; }"
            : "=r"(s1) : "l"((const void*)&rows[1][r_st][c16 * 4]));
        sdst[0] = s0; sdst[1] = s1;
    }

    // prefetch angle 0 into stage 0
    asm volatile("cp.async.ca.shared.global [%0], [%1], 16;\n"
                 :: "r"(sdst[0]), "l"(gsrc_base + 0 * DET) : "memory");
    asm volatile("cp.async.commit_group;\n" ::: "memory");

    const float jf  = (float)(j0 + tx - RAD);
    float xpr[4];
    #pragma unroll
    for (int r = 0; r < 4; r++) xpr[r] = (float)(i0 + ty + 8 * r - RAD);

    float acc[2][4];
    #pragma unroll
    for (int bb = 0; bb < 2; bb++)
        #pragma unroll
        for (int r = 0; r < 4; r++) acc[bb][r] = 0.0f;

    for (int a = 0; a < NTH; a++) {
        const int cur = a & 1;
        if (a + 1 < NTH) {
            asm volatile("cp.async.ca.shared.global [%0], [%1], 16;\n"
                         :: "r"(sdst[cur ^ 1]), "l"(gsrc_base + (a + 1) * DET)
                         : "memory");
            asm volatile("cp.async.commit_group;\n" ::: "memory");
            asm volatile("cp.async.wait_group 1;\n" ::: "memory");
        } else {
            asm volatile("cp.async.wait_group 0;\n" ::: "memory");
        }
        __syncthreads();   // staged rows for angle a now visible to all

        const float c = cs[a];
        const float s = sn[a];
        const float base = fmaf(jf, c, (float)(DET / 2));
        const float* r0 = rows[cur][0];
        const float* r1 = rows[cur][1];

        #pragma unroll
        for (int r = 0; r < 4; r++) {
            float pos = fmaf(-xpr[r], s, base);
            int   idx = __float2int_rd(pos);
            float w   = pos - (float)idx;
            int   sel = ((unsigned)idx <= 511u) ? idx : OOB;
            float a0 = r0[sel], a1 = r0[sel + 1];
            float b0v = r1[sel], b1v = r1[sel + 1];
            acc[0][r] += fmaf(w, a1 - a0, a0);
            acc[1][r] += fmaf(w, b1v - b0v, b0v);
        }
        __syncthreads();   // all done reading stage 'cur' before it is refilled
    }

    const float scale = PI_F / (2.0f * (float)NTH);
    const int j = j0 + tx;
    if (j < OUT) {
        #pragma unroll
        for (int bb = 0; bb < 2; bb++) {
            #pragma unroll
            for (int r = 0; r < 4; r++) {
                int i = i0 + ty + 8 * r;
                if (i < OUT)
                    out[((b0 + bb) * OUT + i) * OUT + j] = acc[bb][r] * scale;
            }
        }
    }
}

extern "C" void kernel_launch(void* const* d_in, const int* in_sizes, int n_in,
                              void* d_out, int out_size)
{
    const float* x = (const float*)d_in[0];
    float* out = (float*)d_out;

    filter_kernel<<<dim3(NTH, B), DET>>>(x);

    dim3 grid((OUT + 31) / 32, (OUT + 31) / 32, B / 2);   // 12 x 12 x 2
    backproj_kernel<<<grid, 256>>>(out);
}

// round 4
// speedup vs baseline: 1.4027x; 1.4027x over previous
#include <cuda_runtime.h>
#include <cstdint>
#include <math.h>

#define DET 512
#define NTH 180
#define B   4
#define OUT 362
#define RAD 181          // OUT//2 per reference
#define PI_F 3.14159265358979323846f

#define ROWLEN 516       // 512 data + 4 zero pad; 16B-divisible
#define OOB    513       // pad slot: row[513]=row[514]=0
#define STG    3         // cp.async ring stages

// filtered projections, layout [b][a][det] (det contiguous)
__device__ float g_filt[B * NTH * DET];

// ---------------------------------------------------------------------------
// Kernel 1: ramp filter as direct symmetric convolution (exact equivalent of
// the reference FFT ramp filter with 512-zero circular pad).
// ---------------------------------------------------------------------------
__global__ void __launch_bounds__(DET) filter_kernel(const float* __restrict__ x)
{
    __shared__ float xs[DET];
    __shared__ float gt[DET];

    const int a = blockIdx.x;
    const int b = blockIdx.y;
    const int k = threadIdx.x;

    // x layout: (B,1,DET,NTH) -> x[b, m, a] = x[(b*DET + m)*NTH + a]
    xs[k] = x[(b * DET + k) * NTH + a];

    float fd = (float)k;
    gt[k] = (k & 1) ? (-2.0f / (PI_F * PI_F * fd * fd)) : 0.0f;
    __syncthreads();

    float s = 0.5f * xs[k];
    const int par = (k & 1) ^ 1;   // m-parity opposite to k
    #pragma unroll 8
    for (int i = 0; i < DET / 2; i++) {
        int m = 2 * i + par;
        int d = k - m; d = d < 0 ? -d : d;
        s = fmaf(gt[d], xs[m], s);
    }
    g_filt[(b * NTH + a) * DET + k] = s;
}

// ---------------------------------------------------------------------------
// Kernel 2: backprojection. 32x32 pixel tile, ALL FOUR batches per block,
// 256 threads, 4 pixel-rows x 4 batches = 16 interps per thread per angle.
// 3-stage cp.async ring -> one __syncthreads per angle.
// pos = (j-RAD)*cos(th) - (i-RAD)*sin(th) + DET/2
// ---------------------------------------------------------------------------
__global__ void __launch_bounds__(256) backproj_kernel(float* __restrict__ out)
{
    __shared__ float rows[STG][B][ROWLEN];   // 3*4*516*4 = 24768 B
    __shared__ float cs[NTH];
    __shared__ float sn[NTH];

    const int j0 = blockIdx.x * 32;
    const int i0 = blockIdx.y * 32;
    const int tid = threadIdx.x;
    const int tx = tid & 31;             // column j within tile
    const int ty = tid >> 5;             // 0..7, pixel-row group

    if (tid < NTH) {
        float ang = (float)tid * (PI_F / 180.0f);
        cs[tid] = cosf(ang);
        sn[tid] = sinf(ang);
    }
    // zero the pad slots (never written by cp.async): STG*B*4 = 48 floats
    if (tid < STG * B * 4) {
        int p  = tid & 3;
        int bb = (tid >> 2) & 3;
        int st = tid >> 4;
        rows[st][bb][512 + p] = 0.0f;
    }

    // staging: each thread copies 2x16B chunks, for batch rows rA and rA+2
    const int rA  = tid >> 7;            // 0 or 1
    const int c16 = tid & 127;           // 16B chunk within the 2KB row
    const float* gA = g_filt + ( rA      * NTH) * DET + c16 * 4;
    const float* gB = g_filt + ((rA + 2) * NTH) * DET + c16 * 4;
    unsigned int dA[STG], dB[STG];
    #pragma unroll
    for (int st = 0; st < STG; st++) {
        unsigned int u;
        asm("{ .reg .u64 t; cvta.to.shared.u64 t, %1; cvt.u32.u64 %0, t; }"
            : "=r"(u) : "l"((const void*)&rows[st][rA][c16 * 4]));
        dA[st] = u;
        asm("{ .reg .u64 t; cvta.to.shared.u64 t, %1; cvt.u32.u64 %0, t; }"
            : "=r"(u) : "l"((const void*)&rows[st][rA + 2][c16 * 4]));
        dB[st] = u;
    }

    // prologue: prefetch angles 0 and 1 into stages 0 and 1
    #pragma unroll
    for (int a = 0; a < 2; a++) {
        asm volatile("cp.async.ca.shared.global [%0], [%1], 16;\n"
                     :: "r"(dA[a]), "l"(gA + a * DET) : "memory");
        asm volatile("cp.async.ca.shared.global [%0], [%1], 16;\n"
                     :: "r"(dB[a]), "l"(gB + a * DET) : "memory");
        asm volatile("cp.async.commit_group;\n" ::: "memory");
    }

    const float jf = (float)(j0 + tx - RAD);
    float xpr[4];
    #pragma unroll
    for (int r = 0; r < 4; r++) xpr[r] = (float)(i0 + ty + 8 * r - RAD);

    float acc[B][4];
    #pragma unroll
    for (int bb = 0; bb < B; bb++)
        #pragma unroll
        for (int r = 0; r < 4; r++) acc[bb][r] = 0.0f;

    int st = 0;
    for (int a = 0; a < NTH; a++) {
        // group for angle a must be complete (a+1 may still be pending)
        if (a < NTH - 2) {
            asm volatile("cp.async.wait_group 1;\n" ::: "memory");
        } else {
            asm volatile("cp.async.wait_group 0;\n" ::: "memory");
        }
        __syncthreads();   // all copies for angle a visible; stage (a+2)%3 free

        if (a + 2 < NTH) {
            int nst = st + 2; if (nst >= STG) nst -= STG;
            asm volatile("cp.async.ca.shared.global [%0], [%1], 16;\n"
                         :: "r"(dA[nst]), "l"(gA + (a + 2) * DET) : "memory");
            asm volatile("cp.async.ca.shared.global [%0], [%1], 16;\n"
                         :: "r"(dB[nst]), "l"(gB + (a + 2) * DET) : "memory");
            asm volatile("cp.async.commit_group;\n" ::: "memory");
        }

        const float c = cs[a];
        const float s = sn[a];
        const float base = fmaf(jf, c, (float)(DET / 2));
        const float* r0 = rows[st][0];
        const float* r1 = rows[st][1];
        const float* r2 = rows[st][2];
        const float* r3 = rows[st][3];

        #pragma unroll
        for (int r = 0; r < 4; r++) {
            float pos = fmaf(-xpr[r], s, base);
            int   idx = __float2int_rd(pos);
            float w   = pos - (float)idx;
            // exact reference gate: fill 0 unless 0 <= pos <= det-1
            int sel = (pos >= 0.0f && pos <= (float)(DET - 1)) ? idx : OOB;
            float v0, v1;
            v0 = r0[sel]; v1 = r0[sel + 1];
            acc[0][r] += fmaf(w, v1 - v0, v0);
            v0 = r1[sel]; v1 = r1[sel + 1];
            acc[1][r] += fmaf(w, v1 - v0, v0);
            v0 = r2[sel]; v1 = r2[sel + 1];
            acc[2][r] += fmaf(w, v1 - v0, v0);
            v0 = r3[sel]; v1 = r3[sel + 1];
            acc[3][r] += fmaf(w, v1 - v0, v0);
        }

        st++; if (st >= STG) st -= STG;
    }

    const float scale = PI_F / (2.0f * (float)NTH);
    const int j = j0 + tx;
    if (j < OUT) {
        #pragma unroll
        for (int bb = 0; bb < B; bb++) {
            #pragma unroll
            for (int r = 0; r < 4; r++) {
                int i = i0 + ty + 8 * r;
                if (i < OUT)
                    out[(bb * OUT + i) * OUT + j] = acc[bb][r] * scale;
            }
        }
    }
}

extern "C" void kernel_launch(void* const* d_in, const int* in_sizes, int n_in,
                              void* d_out, int out_size)
{
    const float* x = (const float*)d_in[0];
    float* out = (float*)d_out;

    filter_kernel<<<dim3(NTH, B), DET>>>(x);

    dim3 grid((OUT + 31) / 32, (OUT + 31) / 32);   // 12 x 12, all batches inside
    backproj_kernel<<<grid, 256>>>(out);
}